// round 9
// baseline (speedup 1.0000x reference)
#include <cuda_runtime.h>
#include <cuda_fp16.h>
#include <cstdint>

#define B_   64
#define T_   512
#define H_   1024
#define L_   4
#define O_   256
#define NCTA 128
#define NTHR 256

#define KC      128                       // K per chunk
#define NCHUNK  16                        // 2048 / 128
#define ASTG    16384                     // A tile 64 rows x 256B (per stage)
#define OFF_SG  (3 * ASTG)                // 49152 : gate preacts 64x128 f32
#define OFF_SC  (OFF_SG + 64 * 128 * 4)   // 81920 : cell state 64x32 f32
#define SMEM_TOTAL (OFF_SC + 8192)        // 90112

// XOR-swizzled index into sG
#define SGIDX(m, n) (((m) << 7) + ((n) ^ (((m) & 3) << 3)))

// ---------------- scratch (static device globals; no allocation) ----------------
// W in per-lane B-fragment layout: [l*32+s][kc=16][kk=8][wn=4][lane=32][q=2 uint4]
__device__ __half2 g_Wfrag[(size_t)128 * 16 * 8 * 4 * 32 * 8];
__device__ __half g_x[(size_t)T_ * B_ * H_];           // x fp16, [t][b][d]
__device__ __half g_h[2 * L_ * B_ * H_];               // h fp16, [parity][l][b][h]
__device__ float  g_bias[L_ * 4 * H_];                 // bih + bhh
__device__ float  g_h3[B_ * H_];                       // final layer-3 h (fp32)
__device__ unsigned g_barGen;
__device__ unsigned g_barCnt;

// ---------------- helpers --------------------------------------------------------
__device__ __forceinline__ uint32_t smem_u32(const void* p) {
    uint32_t a;
    asm("{ .reg .u64 t; cvta.to.shared.u64 t, %1; cvt.u32.u64 %0, t; }" : "=r"(a) : "l"(p));
    return a;
}
__device__ __forceinline__ void cpa16(uint32_t dst, const void* src) {
    asm volatile("cp.async.cg.shared.global [%0], [%1], 16;" :: "r"(dst), "l"(src) : "memory");
}
__device__ __forceinline__ void cp_commit() {
    asm volatile("cp.async.commit_group;" ::: "memory");
}
__device__ __forceinline__ void cp_wait1() {
    asm volatile("cp.async.wait_group 1;" ::: "memory");
}
__device__ __forceinline__ void ldsm4(uint32_t* r, uint32_t a) {
    asm volatile("ldmatrix.sync.aligned.m8n8.x4.shared.b16 {%0,%1,%2,%3}, [%4];"
                 : "=r"(r[0]), "=r"(r[1]), "=r"(r[2]), "=r"(r[3]) : "r"(a));
}
// f16-accumulate HMMA (2 C regs)
__device__ __forceinline__ void mma16816h(uint32_t* c, const uint32_t* a,
                                          uint32_t b0, uint32_t b1) {
    asm volatile(
        "mma.sync.aligned.m16n8k16.row.col.f16.f16.f16.f16 "
        "{%0,%1}, {%2,%3,%4,%5}, {%6,%7}, {%0,%1};\n"
        : "+r"(c[0]), "+r"(c[1])
        : "r"(a[0]), "r"(a[1]), "r"(a[2]), "r"(a[3]), "r"(b0), "r"(b1));
}

// ---------------- split grid barrier ---------------------------------------------
__device__ __forceinline__ unsigned bar_arrive() {
    __threadfence();
    __syncthreads();
    unsigned gen = 0;
    if (threadIdx.x == 0) {
        gen = *((volatile unsigned*)&g_barGen);
        __threadfence();
        unsigned prev = atomicAdd(&g_barCnt, 1u);
        if (prev == NCTA - 1) {
            g_barCnt = 0;
            __threadfence();
            atomicAdd(&g_barGen, 1u);
        }
    }
    return gen;
}
__device__ __forceinline__ void bar_wait(unsigned gen) {
    if (threadIdx.x == 0) {
        while (*((volatile unsigned*)&g_barGen) == gen) { }
    }
    __syncthreads();
}

// ---------------- prep: W fragment layout + x fp16 + fused bias ------------------
__global__ void prep_kernel(const float* __restrict__ x,
                            const float* __restrict__ Wih,
                            const float* __restrict__ Whh,
                            const float* __restrict__ bih,
                            const float* __restrict__ bhh) {
    long long tid = (long long)blockIdx.x * blockDim.x + threadIdx.x;
    long long stride = (long long)gridDim.x * blockDim.x;

    // W fragments: n indexes half2 elements of g_Wfrag
    const long long NW = (long long)128 * 16 * 8 * 4 * 32 * 8;   // 16,777,216
    for (long long n = tid; n < NW; n += stride) {
        int e    = (int)(n & 3);
        int q    = (int)((n >> 2) & 1);
        int lane = (int)((n >> 3) & 31);
        int wn   = (int)((n >> 8) & 3);
        int kk   = (int)((n >> 10) & 7);
        int kc   = (int)((n >> 13) & 15);
        int ls   = (int)(n >> 17);
        int l = ls >> 5, s = ls & 31;
        int j = (wn * 4 + q * 2 + (e >> 1)) * 8 + (lane >> 2);   // 0..127 within slice
        int r = e & 1;
        int k = kc * 128 + kk * 16 + r * 8 + (lane & 3) * 2;
        int row = (j >> 5) * 1024 + s * 32 + (j & 31);           // gate row 0..4095
        float v0, v1;
        if (k < 1024) {
            const float* p = Wih + ((long long)l * 4096 + row) * 1024 + k;
            v0 = p[0]; v1 = p[1];
        } else {
            const float* p = Whh + ((long long)l * 4096 + row) * 1024 + (k - 1024);
            v0 = p[0]; v1 = p[1];
        }
        g_Wfrag[n] = __floats2half2_rn(v0, v1);
    }

    const long long NX = (long long)T_ * B_ * H_;
    for (long long n = tid; n < NX; n += stride) {
        int d = (int)(n & 1023);
        int b = (int)((n >> 10) & 63);
        int t = (int)(n >> 16);
        g_x[n] = __float2half_rn(x[((long long)b * T_ + t) * H_ + d]);
    }

    for (long long n = tid; n < L_ * 4 * H_; n += stride)
        g_bias[n] = bih[n] + bhh[n];
}

// ---------------- persistent LSTM kernel -----------------------------------------
__global__ void __launch_bounds__(NTHR, 1) lstm_kernel() {
    extern __shared__ __align__(1024) char smem[];
    const uint32_t sb = smem_u32(smem);
    const int tid = threadIdx.x;
    const int lane = tid & 31;
    const int wid = tid >> 5;
    const int bid = blockIdx.x;
    const int l = bid >> 5;          // layer
    const int s = bid & 31;          // gate-column slice (32 h cols)

    float* sG = (float*)(smem + OFF_SG);  // [b=64][n=128] XOR-swizzled
    float* sC = (float*)(smem + OFF_SC);  // [b=64][hc=32]

    // zero h double buffer + c state
    {
        const int total = (2 * L_ * B_ * H_) / 8;
        uint4 z = make_uint4(0, 0, 0, 0);
        for (int i = bid * NTHR + tid; i < total; i += NCTA * NTHR)
            ((uint4*)g_h)[i] = z;
        for (int i = tid; i < B_ * 32; i += NTHR) sC[i] = 0.f;
    }

    // elementwise constants
    const int hcl = tid & 31;
    const int eb0 = tid >> 5;
    float bias_g[4];
    #pragma unroll
    for (int g = 0; g < 4; ++g)
        bias_g[g] = g_bias[l * 4096 + g * 1024 + s * 32 + hcl];

    // warp / lane tiling: wm = batch half, wn = gate quarter (32 rows)
    const int wm = wid >> 2;
    const int wn = wid & 3;
    const int t8 = lane >> 3;
    const int r8 = lane & 7;
    const uint32_t swz = (uint32_t)r8;
    const uint32_t tA = (uint32_t)(t8 >> 1);

    uint32_t aBase[3][2];
    #pragma unroll
    for (int st = 0; st < 3; ++st) {
        uint32_t wa = sb + st * ASTG;
        #pragma unroll
        for (int mi = 0; mi < 2; ++mi) {
            int m = wm * 32 + mi * 16 + (t8 & 1) * 8 + r8;
            aBase[st][mi] = wa + m * 256;
        }
    }

    // per-warp W fragment pointer: [ls][kc][kk][wn][lane][2 uint4]
    const uint4* Wf = ((const uint4*)g_Wfrag)
                    + (size_t)(l * 32 + s) * (16 * 8 * 4 * 32 * 2)
                    + (size_t)wn * 64 + (size_t)lane * 2;

    unsigned gen = bar_arrive();
    bar_wait(gen);

    for (int tau = 0; tau < T_ + L_ - 1; ++tau) {
        const int t = tau - l;
        if (t >= 0 && t < T_) {
            const int par = tau & 1;
            const __half* hin = g_h + (par ^ 1) * (L_ * B_ * H_);
            const __half* in  = (l == 0) ? (g_x + (size_t)t * (B_ * H_))
                                         : (hin + (l - 1) * (B_ * H_));
            const __half* rec = hin + l * (B_ * H_);

            auto issueA = [&](int kc, int st) {
                const __half* Asrc = (kc < 8) ? in : rec;
                const int kloc = (kc & 7) * KC;
                uint32_t adst = sb + st * ASTG;
                #pragma unroll
                for (int q = 0; q < 4; ++q) {
                    int f = tid + q * 256;
                    int b = f >> 4, c16 = f & 15;
                    uint32_t d = adst + (uint32_t)(b * 256) + ((uint32_t)(c16 ^ (b & 7)) << 4);
                    cpa16(d, Asrc + (size_t)b * 1024 + kloc + c16 * 8);
                }
            };

            float facc[2][4][4];
            #pragma unroll
            for (int mi = 0; mi < 2; ++mi)
                #pragma unroll
                for (int ni = 0; ni < 4; ++ni)
                    #pragma unroll
                    for (int q = 0; q < 4; ++q) facc[mi][ni][q] = 0.f;

            issueA(0, 0); cp_commit();
            issueA(1, 1); cp_commit();

            // W fragment prefetch ring (2-deep over global kstep index)
            uint4 wbuf[3][2];
            wbuf[0][0] = __ldg(Wf + 0);   wbuf[0][1] = __ldg(Wf + 1);
            wbuf[1][0] = __ldg(Wf + 256); wbuf[1][1] = __ldg(Wf + 257);

            #pragma unroll
            for (int kc = 0; kc < NCHUNK; ++kc) {
                const int st = kc % 3;
                cp_wait1();
                __syncthreads();
                if (kc + 2 < NCHUNK) issueA(kc + 2, (kc + 2) % 3);
                cp_commit();

                uint32_t hacc[2][4][2];
                #pragma unroll
                for (int mi = 0; mi < 2; ++mi)
                    #pragma unroll
                    for (int ni = 0; ni < 4; ++ni)
                        hacc[mi][ni][0] = hacc[mi][ni][1] = 0u;

                #pragma unroll
                for (int kk = 0; kk < 8; ++kk) {
                    const int ki = kc * 8 + kk;
                    const int sl = ki % 3;
                    // prefetch ki+2
                    if (ki + 2 < 128) {
                        const uint4* p = Wf + (size_t)(ki + 2) * 256;
                        wbuf[(ki + 2) % 3][0] = __ldg(p);
                        wbuf[(ki + 2) % 3][1] = __ldg(p + 1);
                    }
                    uint32_t a[2][4];
                    #pragma unroll
                    for (int mi = 0; mi < 2; ++mi)
                        ldsm4(a[mi], aBase[st][mi] + ((((uint32_t)(2 * kk) + tA) ^ swz) << 4));
                    const uint4 w0 = wbuf[sl][0], w1 = wbuf[sl][1];
                    #pragma unroll
                    for (int mi = 0; mi < 2; ++mi) {
                        mma16816h(hacc[mi][0], a[mi], w0.x, w0.y);
                        mma16816h(hacc[mi][1], a[mi], w0.z, w0.w);
                        mma16816h(hacc[mi][2], a[mi], w1.x, w1.y);
                        mma16816h(hacc[mi][3], a[mi], w1.z, w1.w);
                    }
                }

                // promote chunk partials to f32
                #pragma unroll
                for (int mi = 0; mi < 2; ++mi)
                    #pragma unroll
                    for (int ni = 0; ni < 4; ++ni) {
                        float2 f0 = __half22float2(*(__half2*)&hacc[mi][ni][0]);
                        float2 f1 = __half22float2(*(__half2*)&hacc[mi][ni][1]);
                        facc[mi][ni][0] += f0.x;
                        facc[mi][ni][1] += f0.y;
                        facc[mi][ni][2] += f1.x;
                        facc[mi][ni][3] += f1.y;
                    }
            }

            // ---- epilogue: facc -> sG[b][n] ----
            {
                const int grp = lane >> 2, tg = lane & 3;
                #pragma unroll
                for (int mi = 0; mi < 2; ++mi)
                    #pragma unroll
                    for (int ni = 0; ni < 4; ++ni) {
                        int n = wn * 32 + ni * 8 + tg * 2;
                        int m0 = wm * 32 + mi * 16 + grp;
                        *(float2*)&sG[SGIDX(m0, n)]     = make_float2(facc[mi][ni][0], facc[mi][ni][1]);
                        *(float2*)&sG[SGIDX(m0 + 8, n)] = make_float2(facc[mi][ni][2], facc[mi][ni][3]);
                    }
            }
            __syncthreads();

            // ---- elementwise LSTM cell ----
            __half* hout = g_h + par * (L_ * B_ * H_) + l * (B_ * H_);
            #pragma unroll
            for (int b = eb0; b < 64; b += 8) {
                float ai = sG[SGIDX(b, 0 * 32 + hcl)] + bias_g[0];
                float af = sG[SGIDX(b, 1 * 32 + hcl)] + bias_g[1];
                float ag = sG[SGIDX(b, 2 * 32 + hcl)] + bias_g[2];
                float ao = sG[SGIDX(b, 3 * 32 + hcl)] + bias_g[3];
                float ig = 1.f / (1.f + __expf(-ai));
                float fg = 1.f / (1.f + __expf(-af));
                float gg = tanhf(ag);
                float og = 1.f / (1.f + __expf(-ao));
                float cs = fg * sC[b * 32 + hcl] + ig * gg;
                sC[b * 32 + hcl] = cs;
                float hv = og * tanhf(cs);
                int go = b * 1024 + s * 32 + hcl;
                __stcg(hout + go, __float2half_rn(hv));
                if (l == 3 && t == T_ - 1) g_h3[go] = hv;
            }
        }

        gen = bar_arrive();
        bar_wait(gen);
    }
}

// ---------------- final FC: out[b][o] = h3[b] . fc_w[o] + fc_b[o] ----------------
__global__ void fc_kernel(const float* __restrict__ fc_w,
                          const float* __restrict__ fc_b,
                          float* __restrict__ out) {
    __shared__ float hs[H_];
    const int b = blockIdx.x;
    const int o = threadIdx.x;
    for (int k = o; k < H_; k += O_) hs[k] = g_h3[b * H_ + k];
    __syncthreads();
    const float* w = fc_w + (long long)o * H_;
    float a0 = 0.f, a1 = 0.f, a2 = 0.f, a3 = 0.f;
    #pragma unroll 4
    for (int k = 0; k < H_; k += 4) {
        a0 += hs[k + 0] * __ldg(w + k + 0);
        a1 += hs[k + 1] * __ldg(w + k + 1);
        a2 += hs[k + 2] * __ldg(w + k + 2);
        a3 += hs[k + 3] * __ldg(w + k + 3);
    }
    out[b * O_ + o] = fc_b[o] + ((a0 + a1) + (a2 + a3));
}

// ---------------- launch ----------------------------------------------------------
extern "C" void kernel_launch(void* const* d_in, const int* in_sizes, int n_in,
                              void* d_out, int out_size) {
    (void)in_sizes; (void)n_in; (void)out_size;
    const float* x    = (const float*)d_in[0];
    const float* Wih  = (const float*)d_in[1];
    const float* Whh  = (const float*)d_in[2];
    const float* bih  = (const float*)d_in[3];
    const float* bhh  = (const float*)d_in[4];
    const float* fc_w = (const float*)d_in[5];
    const float* fc_b = (const float*)d_in[6];

    cudaFuncSetAttribute(lstm_kernel, cudaFuncAttributeMaxDynamicSharedMemorySize, SMEM_TOTAL);
    prep_kernel<<<2048, 256>>>(x, Wih, Whh, bih, bhh);
    lstm_kernel<<<NCTA, NTHR, SMEM_TOTAL>>>();
    fc_kernel<<<B_, O_>>>(fc_w, fc_b, (float*)d_out);
}

// round 10
// speedup vs baseline: 1.3109x; 1.3109x over previous
#include <cuda_runtime.h>
#include <cuda_fp16.h>
#include <cstdint>

#define B_   64
#define T_   512
#define H_   1024
#define L_   4
#define O_   256
#define NCTA 128
#define NTHR 256

#define KC      128                       // K per chunk
#define NCHUNK  16                        // 2048 / 128
#define WSTG    32768                     // W tile 128 rows x 256B
#define ASTG    16384                     // A tile  64 rows x 256B
#define STG     (WSTG + ASTG)             // 49152 per stage
#define OFF_SG  (3 * STG)                 // 147456 : gate preacts 64x128 f32
#define OFF_SC  (OFF_SG + 64 * 128 * 4)   // 180224 : cell state 64x32 f32
#define SMEM_TOTAL (OFF_SC + 8192)        // 188416

// XOR-swizzled index into sG: 2-way-optimal for float2 epilogue stores,
// conflict-free for per-lane cell reads.
#define SGIDX(m, n) (((m) << 7) + ((n) ^ (((m) & 3) << 3)))

// ---------------- scratch (static device globals; no allocation) ----------------
__device__ __half g_Wc[(size_t)L_ * 32 * 128 * 2048];  // [l][s][j=128][k=2048] fp16
__device__ __half g_x[(size_t)T_ * B_ * H_];           // x fp16, [t][b][d]
__device__ __half g_h[2 * L_ * B_ * H_];               // h fp16, [parity][l][b][h]
__device__ float  g_bias[L_ * 4 * H_];                 // bih + bhh
__device__ float  g_h3[B_ * H_];                       // final layer-3 h (fp32)
__device__ unsigned g_barGen;
__device__ unsigned g_barCnt;

// ---------------- helpers --------------------------------------------------------
__device__ __forceinline__ uint32_t smem_u32(const void* p) {
    uint32_t a;
    asm("{ .reg .u64 t; cvta.to.shared.u64 t, %1; cvt.u32.u64 %0, t; }" : "=r"(a) : "l"(p));
    return a;
}
__device__ __forceinline__ void cpa16(uint32_t dst, const void* src) {
    asm volatile("cp.async.cg.shared.global [%0], [%1], 16;" :: "r"(dst), "l"(src) : "memory");
}
__device__ __forceinline__ void cp_commit() {
    asm volatile("cp.async.commit_group;" ::: "memory");
}
__device__ __forceinline__ void cp_wait1() {
    asm volatile("cp.async.wait_group 1;" ::: "memory");
}
__device__ __forceinline__ void ldsm4(uint32_t* r, uint32_t a) {
    asm volatile("ldmatrix.sync.aligned.m8n8.x4.shared.b16 {%0,%1,%2,%3}, [%4];"
                 : "=r"(r[0]), "=r"(r[1]), "=r"(r[2]), "=r"(r[3]) : "r"(a));
}
// f16-accumulate HMMA (2 C regs)
__device__ __forceinline__ void mma16816h(uint32_t* c, const uint32_t* a,
                                          uint32_t b0, uint32_t b1) {
    asm volatile(
        "mma.sync.aligned.m16n8k16.row.col.f16.f16.f16.f16 "
        "{%0,%1}, {%2,%3,%4,%5}, {%6,%7}, {%0,%1};\n"
        : "+r"(c[0]), "+r"(c[1])
        : "r"(a[0]), "r"(a[1]), "r"(a[2]), "r"(a[3]), "r"(b0), "r"(b1));
}

// ---------------- split grid barrier (128 CTAs, 1/SM, all resident) --------------
__device__ __forceinline__ unsigned bar_arrive() {
    __threadfence();
    __syncthreads();
    unsigned gen = 0;
    if (threadIdx.x == 0) {
        gen = *((volatile unsigned*)&g_barGen);
        __threadfence();
        unsigned prev = atomicAdd(&g_barCnt, 1u);
        if (prev == NCTA - 1) {
            g_barCnt = 0;
            __threadfence();
            atomicAdd(&g_barGen, 1u);
        }
    }
    return gen;
}
__device__ __forceinline__ void bar_wait(unsigned gen) {
    if (threadIdx.x == 0) {
        while (*((volatile unsigned*)&g_barGen) == gen) { }
    }
    __syncthreads();
}

// ---------------- prep: weight swizzle + x fp16 + fused bias ---------------------
__global__ void prep_kernel(const float* __restrict__ x,
                            const float* __restrict__ Wih,
                            const float* __restrict__ Whh,
                            const float* __restrict__ bih,
                            const float* __restrict__ bhh) {
    long long tid = (long long)blockIdx.x * blockDim.x + threadIdx.x;
    long long stride = (long long)gridDim.x * blockDim.x;

    const long long NW = (long long)L_ * 32 * 128 * 2048;
    for (long long n = tid; n < NW; n += stride) {
        int k = (int)(n & 2047);
        int j = (int)((n >> 11) & 127);
        int s = (int)((n >> 18) & 31);
        int l = (int)(n >> 23);
        int g = j >> 5, jj = j & 31;
        int row = g * 1024 + s * 32 + jj;
        float v = (k < 1024)
            ? Wih[((long long)l * 4096 + row) * 1024 + k]
            : Whh[((long long)l * 4096 + row) * 1024 + (k - 1024)];
        g_Wc[n] = __float2half_rn(v);
    }

    const long long NX = (long long)T_ * B_ * H_;
    for (long long n = tid; n < NX; n += stride) {
        int d = (int)(n & 1023);
        int b = (int)((n >> 10) & 63);
        int t = (int)(n >> 16);
        g_x[n] = __float2half_rn(x[((long long)b * T_ + t) * H_ + d]);
    }

    for (long long n = tid; n < L_ * 4 * H_; n += stride)
        g_bias[n] = bih[n] + bhh[n];
}

// ---------------- persistent LSTM kernel -----------------------------------------
__global__ void __launch_bounds__(NTHR, 1) lstm_kernel() {
    extern __shared__ __align__(1024) char smem[];
    const uint32_t sb = smem_u32(smem);
    const int tid = threadIdx.x;
    const int lane = tid & 31;
    const int wid = tid >> 5;
    const int bid = blockIdx.x;
    const int l = bid >> 5;          // layer
    const int s = bid & 31;          // gate-column slice (32 h cols)

    float* sG = (float*)(smem + OFF_SG);  // [b=64][n=128] XOR-swizzled
    float* sC = (float*)(smem + OFF_SC);  // [b=64][hc=32]

    // zero h double buffer + c state
    {
        const int total = (2 * L_ * B_ * H_) / 8;
        uint4 z = make_uint4(0, 0, 0, 0);
        for (int i = bid * NTHR + tid; i < total; i += NCTA * NTHR)
            ((uint4*)g_h)[i] = z;
        for (int i = tid; i < B_ * 32; i += NTHR) sC[i] = 0.f;
    }

    // elementwise constants
    const int hcl = tid & 31;
    const int eb0 = tid >> 5;
    float bias_g[4];
    #pragma unroll
    for (int g = 0; g < 4; ++g)
        bias_g[g] = g_bias[l * 4096 + g * 1024 + s * 32 + hcl];

    // warp / lane tiling (2x4 grid of 32x32 tiles — LDSM-minimal)
    const int wm = wid >> 2;
    const int wn = wid & 3;
    const int t8 = lane >> 3;
    const int r8 = lane & 7;
    const uint32_t swz = (uint32_t)r8;
    const uint32_t tA = (uint32_t)(t8 >> 1);
    const uint32_t tB = (uint32_t)(t8 & 1);

    uint32_t aBase[3][2], bBase[3][2];
    #pragma unroll
    for (int st = 0; st < 3; ++st) {
        uint32_t wa = sb + st * STG;
        #pragma unroll
        for (int mi = 0; mi < 2; ++mi) {
            int m = wm * 32 + mi * 16 + (t8 & 1) * 8 + r8;
            aBase[st][mi] = wa + WSTG + m * 256;
        }
        #pragma unroll
        for (int p = 0; p < 2; ++p) {
            int n = wn * 32 + p * 16 + (t8 >> 1) * 8 + r8;
            bBase[st][p] = wa + n * 256;
        }
    }

    const __half* Wbase = g_Wc + (size_t)(l * 32 + s) * 128 * 2048;

    // W staging (tick-invariant — safe to prefetch across barriers)
    auto issueW = [&](int kc, int st) {
        const __half* Wsrc = Wbase + kc * KC;
        uint32_t wdst = sb + st * STG;
        #pragma unroll
        for (int q = 0; q < 8; ++q) {
            int f = tid + q * 256;
            int j = f >> 4, c16 = f & 15;
            uint32_t d = wdst + (uint32_t)(j * 256) + ((uint32_t)(c16 ^ (j & 7)) << 4);
            cpa16(d, Wsrc + (size_t)j * 2048 + c16 * 8);
        }
    };

    // ---- initial barrier + first-tick W prefetch ----
    unsigned gen = bar_arrive();
    if (l == 0) { issueW(0, 0); issueW(1, 1); }
    bar_wait(gen);

    for (int tau = 0; tau < T_ + L_ - 1; ++tau) {
        const int t = tau - l;
        if (t >= 0 && t < T_) {
            const int par = tau & 1;
            const __half* hin = g_h + (par ^ 1) * (L_ * B_ * H_);
            const __half* in  = (l == 0) ? (g_x + (size_t)t * (B_ * H_))
                                         : (hin + (l - 1) * (B_ * H_));
            const __half* rec = hin + l * (B_ * H_);

            auto issueA = [&](int kc, int st) {
                const __half* Asrc = (kc < 8) ? in : rec;
                const int kloc = (kc & 7) * KC;
                uint32_t adst = sb + st * STG + WSTG;
                #pragma unroll
                for (int q = 0; q < 4; ++q) {
                    int f = tid + q * 256;
                    int b = f >> 4, c16 = f & 15;
                    uint32_t d = adst + (uint32_t)(b * 256) + ((uint32_t)(c16 ^ (b & 7)) << 4);
                    cpa16(d, Asrc + (size_t)b * 1024 + kloc + c16 * 8);
                }
            };

            float facc[2][4][4];
            #pragma unroll
            for (int mi = 0; mi < 2; ++mi)
                #pragma unroll
                for (int ni = 0; ni < 4; ++ni)
                    #pragma unroll
                    for (int q = 0; q < 4; ++q) facc[mi][ni][q] = 0.f;

            // W0/W1 already in flight (issued at the barrier). Add A parts.
            issueA(0, 0); cp_commit();      // group = {W0, W1, A0}
            issueA(1, 1); cp_commit();      // group = {A1}

            #pragma unroll
            for (int kc = 0; kc < NCHUNK; ++kc) {
                const int st = kc % 3;
                cp_wait1();
                __syncthreads();
                if (kc + 2 < NCHUNK) { issueW(kc + 2, (kc + 2) % 3); issueA(kc + 2, (kc + 2) % 3); }
                cp_commit();

                // f16 chunk accumulators
                uint32_t hacc[2][4][2];
                #pragma unroll
                for (int mi = 0; mi < 2; ++mi)
                    #pragma unroll
                    for (int ni = 0; ni < 4; ++ni)
                        hacc[mi][ni][0] = hacc[mi][ni][1] = 0u;

                // fragment double buffer: load kk+1 while MMAs run on kk
                uint32_t afr[2][2][4], bfr[2][2][4];
                #pragma unroll
                for (int mi = 0; mi < 2; ++mi)
                    ldsm4(afr[0][mi], aBase[st][mi] + ((tA ^ swz) << 4));
                #pragma unroll
                for (int p = 0; p < 2; ++p)
                    ldsm4(bfr[0][p], bBase[st][p] + ((tB ^ swz) << 4));

                #pragma unroll
                for (int kk = 0; kk < 8; ++kk) {
                    const int cb = kk & 1;
                    if (kk < 7) {
                        const uint32_t ko = (uint32_t)(2 * (kk + 1));
                        #pragma unroll
                        for (int mi = 0; mi < 2; ++mi)
                            ldsm4(afr[cb ^ 1][mi], aBase[st][mi] + (((ko + tA) ^ swz) << 4));
                        #pragma unroll
                        for (int p = 0; p < 2; ++p)
                            ldsm4(bfr[cb ^ 1][p], bBase[st][p] + (((ko + tB) ^ swz) << 4));
                    }
                    #pragma unroll
                    for (int mi = 0; mi < 2; ++mi)
                        #pragma unroll
                        for (int p = 0; p < 2; ++p) {
                            mma16816h(hacc[mi][2 * p],     afr[cb][mi], bfr[cb][p][0], bfr[cb][p][1]);
                            mma16816h(hacc[mi][2 * p + 1], afr[cb][mi], bfr[cb][p][2], bfr[cb][p][3]);
                        }
                }

                // promote chunk partials to f32
                #pragma unroll
                for (int mi = 0; mi < 2; ++mi)
                    #pragma unroll
                    for (int ni = 0; ni < 4; ++ni) {
                        float2 f0 = __half22float2(*(__half2*)&hacc[mi][ni][0]);
                        float2 f1 = __half22float2(*(__half2*)&hacc[mi][ni][1]);
                        facc[mi][ni][0] += f0.x;
                        facc[mi][ni][1] += f0.y;
                        facc[mi][ni][2] += f1.x;
                        facc[mi][ni][3] += f1.y;
                    }
            }

            // ---- epilogue: facc -> sG[b][n] ----
            {
                const int grp = lane >> 2, tg = lane & 3;
                #pragma unroll
                for (int mi = 0; mi < 2; ++mi)
                    #pragma unroll
                    for (int ni = 0; ni < 4; ++ni) {
                        int n = wn * 32 + ni * 8 + tg * 2;
                        int m0 = wm * 32 + mi * 16 + grp;
                        *(float2*)&sG[SGIDX(m0, n)]     = make_float2(facc[mi][ni][0], facc[mi][ni][1]);
                        *(float2*)&sG[SGIDX(m0 + 8, n)] = make_float2(facc[mi][ni][2], facc[mi][ni][3]);
                    }
            }
            __syncthreads();

            // ---- elementwise LSTM cell ----
            __half* hout = g_h + par * (L_ * B_ * H_) + l * (B_ * H_);
            #pragma unroll
            for (int b = eb0; b < 64; b += 8) {
                float ai = sG[SGIDX(b, 0 * 32 + hcl)] + bias_g[0];
                float af = sG[SGIDX(b, 1 * 32 + hcl)] + bias_g[1];
                float ag = sG[SGIDX(b, 2 * 32 + hcl)] + bias_g[2];
                float ao = sG[SGIDX(b, 3 * 32 + hcl)] + bias_g[3];
                float ig = 1.f / (1.f + __expf(-ai));
                float fg = 1.f / (1.f + __expf(-af));
                float gg = tanhf(ag);
                float og = 1.f / (1.f + __expf(-ao));
                float cs = fg * sC[b * 32 + hcl] + ig * gg;
                sC[b * 32 + hcl] = cs;
                float hv = og * tanhf(cs);
                int go = b * 1024 + s * 32 + hcl;
                __stcg(hout + go, __float2half_rn(hv));
                if (l == 3 && t == T_ - 1) g_h3[go] = hv;
            }
        }

        // ---- barrier with next-tick W prefetch hidden in the arrive/wait gap ----
        gen = bar_arrive();
        const int t2 = tau + 1 - l;
        if (t2 >= 0 && t2 < T_) { issueW(0, 0); issueW(1, 1); }
        bar_wait(gen);
    }
}

// ---------------- final FC: out[b][o] = h3[b] . fc_w[o] + fc_b[o] ----------------
__global__ void fc_kernel(const float* __restrict__ fc_w,
                          const float* __restrict__ fc_b,
                          float* __restrict__ out) {
    __shared__ float hs[H_];
    const int b = blockIdx.x;
    const int o = threadIdx.x;
    for (int k = o; k < H_; k += O_) hs[k] = g_h3[b * H_ + k];
    __syncthreads();
    const float* w = fc_w + (long long)o * H_;
    float a0 = 0.f, a1 = 0.f, a2 = 0.f, a3 = 0.f;
    #pragma unroll 4
    for (int k = 0; k < H_; k += 4) {
        a0 += hs[k + 0] * __ldg(w + k + 0);
        a1 += hs[k + 1] * __ldg(w + k + 1);
        a2 += hs[k + 2] * __ldg(w + k + 2);
        a3 += hs[k + 3] * __ldg(w + k + 3);
    }
    out[b * O_ + o] = fc_b[o] + ((a0 + a1) + (a2 + a3));
}

// ---------------- launch ----------------------------------------------------------
extern "C" void kernel_launch(void* const* d_in, const int* in_sizes, int n_in,
                              void* d_out, int out_size) {
    (void)in_sizes; (void)n_in; (void)out_size;
    const float* x    = (const float*)d_in[0];
    const float* Wih  = (const float*)d_in[1];
    const float* Whh  = (const float*)d_in[2];
    const float* bih  = (const float*)d_in[3];
    const float* bhh  = (const float*)d_in[4];
    const float* fc_w = (const float*)d_in[5];
    const float* fc_b = (const float*)d_in[6];

    cudaFuncSetAttribute(lstm_kernel, cudaFuncAttributeMaxDynamicSharedMemorySize, SMEM_TOTAL);
    prep_kernel<<<2048, 256>>>(x, Wih, Whh, bih, bhh);
    lstm_kernel<<<NCTA, NTHR, SMEM_TOTAL>>>();
    fc_kernel<<<B_, O_>>>(fc_w, fc_b, (float*)d_out);
}

// round 11
// speedup vs baseline: 1.3917x; 1.0616x over previous
#include <cuda_runtime.h>
#include <cuda_fp16.h>
#include <cstdint>

#define B_   64
#define T_   512
#define H_   1024
#define L_   4
#define O_   256
#define NCTA 148
#define NTHR 256

#define KC      128
#define NCHUNK  16
#define WROWS_MAX 112
#define WSTG2   (WROWS_MAX * 256)          // 28672 per stage (padded)
#define ASTG    16384                      // A tile 64 x 256B
#define STG     (WSTG2 + ASTG)             // 45056
#define OFF_SG  (3 * STG)                  // 135168
#define SG_STRIDE 116                      // f32 units; conflict-spread
#define OFF_SC  (OFF_SG + 64 * SG_STRIDE * 4)   // 164864
#define SMEM_TOTAL (OFF_SC + 7168)         // 172032

// ---------------- scratch (static device globals; no allocation) ----------------
// W per-slice tiles: [(l*37+sl)][j<112 padded][k=2048] fp16
__device__ __half g_Wc[(size_t)NCTA * WROWS_MAX * 2048];
__device__ __half g_x[(size_t)T_ * B_ * H_];           // x fp16, [t][b][d]
__device__ __half g_h[2 * L_ * B_ * H_];               // h fp16, [parity][l][b][h]
__device__ float  g_bias[L_ * 4 * H_];                 // bih + bhh
__device__ float  g_h3[B_ * H_];                       // final layer-3 h (fp32)
__device__ unsigned g_barGen;
__device__ unsigned g_barCnt;

// ---------------- helpers --------------------------------------------------------
__device__ __forceinline__ uint32_t smem_u32(const void* p) {
    uint32_t a;
    asm("{ .reg .u64 t; cvta.to.shared.u64 t, %1; cvt.u32.u64 %0, t; }" : "=r"(a) : "l"(p));
    return a;
}
__device__ __forceinline__ void cpa16(uint32_t dst, const void* src) {
    asm volatile("cp.async.cg.shared.global [%0], [%1], 16;" :: "r"(dst), "l"(src) : "memory");
}
__device__ __forceinline__ void cp_commit() {
    asm volatile("cp.async.commit_group;" ::: "memory");
}
__device__ __forceinline__ void cp_wait1() {
    asm volatile("cp.async.wait_group 1;" ::: "memory");
}
__device__ __forceinline__ void ldsm4(uint32_t* r, uint32_t a) {
    asm volatile("ldmatrix.sync.aligned.m8n8.x4.shared.b16 {%0,%1,%2,%3}, [%4];"
                 : "=r"(r[0]), "=r"(r[1]), "=r"(r[2]), "=r"(r[3]) : "r"(a));
}
__device__ __forceinline__ void ldsm2(uint32_t* r, uint32_t a) {
    asm volatile("ldmatrix.sync.aligned.m8n8.x2.shared.b16 {%0,%1}, [%2];"
                 : "=r"(r[0]), "=r"(r[1]) : "r"(a));
}
__device__ __forceinline__ void mma16816(float* c, const uint32_t* a, uint32_t b0, uint32_t b1) {
    asm volatile(
        "mma.sync.aligned.m16n8k16.row.col.f32.f16.f16.f32 "
        "{%0,%1,%2,%3}, {%4,%5,%6,%7}, {%8,%9}, {%0,%1,%2,%3};\n"
        : "+f"(c[0]), "+f"(c[1]), "+f"(c[2]), "+f"(c[3])
        : "r"(a[0]), "r"(a[1]), "r"(a[2]), "r"(a[3]), "r"(b0), "r"(b1));
}
__device__ __forceinline__ float tanh_fast(float x) {
    float y;
    asm("tanh.approx.f32 %0, %1;" : "=f"(y) : "f"(x));
    return y;
}
__device__ __forceinline__ float sig_fast(float x) {
    return 0.5f * tanh_fast(0.5f * x) + 0.5f;
}

// ---------------- split grid barrier (148 CTAs, 1/SM, all resident) --------------
__device__ __forceinline__ unsigned bar_arrive() {
    __threadfence();
    __syncthreads();
    unsigned gen = 0;
    if (threadIdx.x == 0) {
        gen = *((volatile unsigned*)&g_barGen);
        __threadfence();
        unsigned prev = atomicAdd(&g_barCnt, 1u);
        if (prev == NCTA - 1) {
            g_barCnt = 0;
            __threadfence();
            atomicAdd(&g_barGen, 1u);
        }
    }
    return gen;
}
__device__ __forceinline__ void bar_wait(unsigned gen) {
    if (threadIdx.x == 0) {
        while (*((volatile unsigned*)&g_barGen) == gen) { }
    }
    __syncthreads();
}

// slice geometry: 34 slices of 28 cols + 3 of 24 cols per layer
__device__ __forceinline__ void slice_geom(int sl, int& width, int& coff) {
    if (sl < 34) { width = 28; coff = 28 * sl; }
    else         { width = 24; coff = 952 + 24 * (sl - 34); }
}

// ---------------- prep: W slice tiles + x fp16 + fused bias ----------------------
__global__ void prep_kernel(const float* __restrict__ x,
                            const float* __restrict__ Wih,
                            const float* __restrict__ Whh,
                            const float* __restrict__ bih,
                            const float* __restrict__ bhh) {
    long long tid = (long long)blockIdx.x * blockDim.x + threadIdx.x;
    long long stride = (long long)gridDim.x * blockDim.x;

    const long long NW = (long long)NCTA * WROWS_MAX * 2048;   // 33,947,648
    for (long long n = tid; n < NW; n += stride) {
        int k  = (int)(n & 2047);
        unsigned rj = (unsigned)(n >> 11);
        unsigned j   = rj % 112u;
        unsigned lsl = rj / 112u;
        unsigned l  = lsl / 37u;
        unsigned sl = lsl - l * 37u;
        int width, coff;
        slice_geom((int)sl, width, coff);
        if ((int)j < 4 * width) {
            int g = ((int)j >= width) + ((int)j >= 2 * width) + ((int)j >= 3 * width);
            int c = (int)j - g * width;
            int row = g * 1024 + coff + c;
            float v = (k < 1024)
                ? Wih[((long long)l * 4096 + row) * 1024 + k]
                : Whh[((long long)l * 4096 + row) * 1024 + (k - 1024)];
            g_Wc[n] = __float2half_rn(v);
        }
    }

    const long long NX = (long long)T_ * B_ * H_;
    for (long long n = tid; n < NX; n += stride) {
        int d = (int)(n & 1023);
        int b = (int)((n >> 10) & 63);
        int t = (int)(n >> 16);
        g_x[n] = __float2half_rn(x[((long long)b * T_ + t) * H_ + d]);
    }

    for (long long n = tid; n < L_ * 4 * H_; n += stride)
        g_bias[n] = bih[n] + bhh[n];
}

// ---------------- persistent LSTM kernel -----------------------------------------
__global__ void __launch_bounds__(NTHR, 1) lstm_kernel() {
    extern __shared__ __align__(1024) char smem[];
    const uint32_t sb = smem_u32(smem);
    const int tid = threadIdx.x;
    const int lane = tid & 31;
    const int wid = tid >> 5;
    const int bid = blockIdx.x;
    const int l  = bid / 37;         // layer
    const int sl = bid - l * 37;     // slice within layer
    int width, coff;
    slice_geom(sl, width, coff);
    const int rows = 4 * width;      // 112 or 96
    const int nW = rows >> 4;        // cpa16 iters per thread for W (7 or 6)

    float* sG = (float*)(smem + OFF_SG);  // [b=64][SG_STRIDE]
    float* sC = (float*)(smem + OFF_SC);  // [b=64][28]

    // zero h double buffer + c state
    {
        const int total = (2 * L_ * B_ * H_) / 8;
        uint4 z = make_uint4(0, 0, 0, 0);
        for (int i = bid * NTHR + tid; i < total; i += NCTA * NTHR)
            ((uint4*)g_h)[i] = z;
        for (int i = tid; i < 64 * 28; i += NTHR) sC[i] = 0.f;
    }

    // elementwise constants
    const int hcl = tid & 31;
    const int eb0 = tid >> 5;
    float bias_g[4] = {0.f, 0.f, 0.f, 0.f};
    if (hcl < width) {
        #pragma unroll
        for (int g = 0; g < 4; ++g)
            bias_g[g] = g_bias[l * 4096 + g * 1024 + coff + hcl];
    }

    // warp maps: SMSP = wid&3; pairs (w, w+4) get q totals 7 for width 28
    const int wn_map[8] = {0, 1, 2, 3, 2, 3, 0, 1};
    const int wn = wn_map[wid];
    const int wm = wid >> 2;         // 0..3 -> m-half 0, 4..7 -> m-half 1
    int qn, noff;
    if (width == 28) {
        qn = (wn < 2) ? 4 : 3;
        noff = (wn == 0) ? 0 : (wn == 1) ? 32 : (wn == 2) ? 64 : 88;
    } else {
        qn = 3;
        noff = wn * 24;
    }

    const int t8 = lane >> 3;
    const int r8 = lane & 7;
    const uint32_t swz = (uint32_t)r8;
    const uint32_t tA = (uint32_t)(t8 >> 1);
    const uint32_t tB = (uint32_t)(t8 & 1);

    uint32_t aBase[3][2], bBase[3][2], b2Base[3];
    #pragma unroll
    for (int st = 0; st < 3; ++st) {
        uint32_t wa = sb + st * STG;
        #pragma unroll
        for (int mi = 0; mi < 2; ++mi) {
            int m = wm * 32 + mi * 16 + (t8 & 1) * 8 + r8;
            aBase[st][mi] = wa + WSTG2 + m * 256;
        }
        #pragma unroll
        for (int p = 0; p < 2; ++p) {
            int n = noff + p * 16 + (t8 >> 1) * 8 + r8;
            bBase[st][p] = wa + n * 256;
        }
        // x2 tail: n8 block at noff+16, lanes 0-15 supply addresses
        int n2 = noff + 16 + (lane & 7);
        b2Base[st] = wa + n2 * 256;
    }
    const uint32_t tB2 = (uint32_t)((lane >> 3) & 1);

    const __half* Wbase = g_Wc + (size_t)bid * WROWS_MAX * 2048;

    // W staging (tick-invariant — prefetch across barriers)
    auto issueW = [&](int kc, int st) {
        const __half* Wsrc = Wbase + kc * KC;
        uint32_t wdst = sb + st * STG;
        for (int q = 0; q < nW; ++q) {
            int f = tid + q * 256;
            int j = f >> 4, c16 = f & 15;
            uint32_t d = wdst + (uint32_t)(j * 256) + ((uint32_t)(c16 ^ (j & 7)) << 4);
            cpa16(d, Wsrc + (size_t)j * 2048 + c16 * 8);
        }
    };

    unsigned gen = bar_arrive();
    if (l == 0) { issueW(0, 0); issueW(1, 1); }
    bar_wait(gen);

    for (int tau = 0; tau < T_ + L_ - 1; ++tau) {
        const int t = tau - l;
        if (t >= 0 && t < T_) {
            const int par = tau & 1;
            const __half* hin = g_h + (par ^ 1) * (L_ * B_ * H_);
            const __half* in  = (l == 0) ? (g_x + (size_t)t * (B_ * H_))
                                         : (hin + (l - 1) * (B_ * H_));
            const __half* rec = hin + l * (B_ * H_);

            auto issueA = [&](int kc, int st) {
                const __half* Asrc = (kc < 8) ? in : rec;
                const int kloc = (kc & 7) * KC;
                uint32_t adst = sb + st * STG + WSTG2;
                #pragma unroll
                for (int q = 0; q < 4; ++q) {
                    int f = tid + q * 256;
                    int b = f >> 4, c16 = f & 15;
                    uint32_t d = adst + (uint32_t)(b * 256) + ((uint32_t)(c16 ^ (b & 7)) << 4);
                    cpa16(d, Asrc + (size_t)b * 1024 + kloc + c16 * 8);
                }
            };

            float acc[2][4][4];
            #pragma unroll
            for (int mi = 0; mi < 2; ++mi)
                #pragma unroll
                for (int ni = 0; ni < 4; ++ni)
                    #pragma unroll
                    for (int q = 0; q < 4; ++q) acc[mi][ni][q] = 0.f;

            issueA(0, 0); cp_commit();      // group = {W0, W1, A0}
            issueA(1, 1); cp_commit();      // group = {A1}

            #pragma unroll
            for (int kc = 0; kc < NCHUNK; ++kc) {
                const int st = kc % 3;
                cp_wait1();
                __syncthreads();
                if (kc + 2 < NCHUNK) { issueW(kc + 2, (kc + 2) % 3); issueA(kc + 2, (kc + 2) % 3); }
                cp_commit();

                if (qn == 4) {
                    #pragma unroll
                    for (int kk = 0; kk < 8; ++kk) {
                        const uint32_t acol = (((uint32_t)(2 * kk) + tA) ^ swz) << 4;
                        const uint32_t bcol = (((uint32_t)(2 * kk) + tB) ^ swz) << 4;
                        uint32_t a[2][4], bf[2][4];
                        ldsm4(a[0], aBase[st][0] + acol);
                        ldsm4(a[1], aBase[st][1] + acol);
                        ldsm4(bf[0], bBase[st][0] + bcol);
                        ldsm4(bf[1], bBase[st][1] + bcol);
                        #pragma unroll
                        for (int mi = 0; mi < 2; ++mi) {
                            mma16816(acc[mi][0], a[mi], bf[0][0], bf[0][1]);
                            mma16816(acc[mi][1], a[mi], bf[0][2], bf[0][3]);
                            mma16816(acc[mi][2], a[mi], bf[1][0], bf[1][1]);
                            mma16816(acc[mi][3], a[mi], bf[1][2], bf[1][3]);
                        }
                    }
                } else {
                    #pragma unroll
                    for (int kk = 0; kk < 8; ++kk) {
                        const uint32_t acol = (((uint32_t)(2 * kk) + tA) ^ swz) << 4;
                        const uint32_t bcol = (((uint32_t)(2 * kk) + tB) ^ swz) << 4;
                        const uint32_t b2col = (((uint32_t)(2 * kk) + tB2) ^ swz) << 4;
                        uint32_t a[2][4], bf[4], b2[2];
                        ldsm4(a[0], aBase[st][0] + acol);
                        ldsm4(a[1], aBase[st][1] + acol);
                        ldsm4(bf, bBase[st][0] + bcol);
                        ldsm2(b2, b2Base[st] + b2col);
                        #pragma unroll
                        for (int mi = 0; mi < 2; ++mi) {
                            mma16816(acc[mi][0], a[mi], bf[0], bf[1]);
                            mma16816(acc[mi][1], a[mi], bf[2], bf[3]);
                            mma16816(acc[mi][2], a[mi], b2[0], b2[1]);
                        }
                    }
                }
            }

            // ---- epilogue: acc -> sG[b][n] ----
            {
                const int grp = lane >> 2, tg = lane & 3;
                #pragma unroll
                for (int mi = 0; mi < 2; ++mi)
                    #pragma unroll
                    for (int ni = 0; ni < 4; ++ni) {
                        if (ni < qn) {
                            int n = noff + ni * 8 + tg * 2;
                            int m0 = wm * 32 + mi * 16 + grp;
                            *(float2*)&sG[m0 * SG_STRIDE + n] =
                                make_float2(acc[mi][ni][0], acc[mi][ni][1]);
                            *(float2*)&sG[(m0 + 8) * SG_STRIDE + n] =
                                make_float2(acc[mi][ni][2], acc[mi][ni][3]);
                        }
                    }
            }
            __syncthreads();

            // ---- elementwise LSTM cell ----
            if (hcl < width) {
                __half* hout = g_h + par * (L_ * B_ * H_) + l * (B_ * H_);
                #pragma unroll
                for (int b = eb0; b < 64; b += 8) {
                    float ai = sG[b * SG_STRIDE + 0 * width + hcl] + bias_g[0];
                    float af = sG[b * SG_STRIDE + 1 * width + hcl] + bias_g[1];
                    float ag = sG[b * SG_STRIDE + 2 * width + hcl] + bias_g[2];
                    float ao = sG[b * SG_STRIDE + 3 * width + hcl] + bias_g[3];
                    float ig = sig_fast(ai);
                    float fg = sig_fast(af);
                    float gg = tanh_fast(ag);
                    float og = sig_fast(ao);
                    float cs = fg * sC[b * 28 + hcl] + ig * gg;
                    sC[b * 28 + hcl] = cs;
                    float hv = og * tanh_fast(cs);
                    int go = b * 1024 + coff + hcl;
                    __stcg(hout + go, __float2half_rn(hv));
                    if (l == 3 && t == T_ - 1) g_h3[go] = hv;
                }
            }
        }

        // barrier with next-tick W prefetch hidden in the arrive/wait gap
        gen = bar_arrive();
        const int t2 = tau + 1 - l;
        if (t2 >= 0 && t2 < T_) { issueW(0, 0); issueW(1, 1); }
        bar_wait(gen);
    }
}

// ---------------- final FC: out[b][o] = h3[b] . fc_w[o] + fc_b[o] ----------------
__global__ void fc_kernel(const float* __restrict__ fc_w,
                          const float* __restrict__ fc_b,
                          float* __restrict__ out) {
    __shared__ float hs[H_];
    const int b = blockIdx.x;
    const int o = threadIdx.x;
    for (int k = o; k < H_; k += O_) hs[k] = g_h3[b * H_ + k];
    __syncthreads();
    const float* w = fc_w + (long long)o * H_;
    float a0 = 0.f, a1 = 0.f, a2 = 0.f, a3 = 0.f;
    #pragma unroll 4
    for (int k = 0; k < H_; k += 4) {
        a0 += hs[k + 0] * __ldg(w + k + 0);
        a1 += hs[k + 1] * __ldg(w + k + 1);
        a2 += hs[k + 2] * __ldg(w + k + 2);
        a3 += hs[k + 3] * __ldg(w + k + 3);
    }
    out[b * O_ + o] = fc_b[o] + ((a0 + a1) + (a2 + a3));
}

// ---------------- launch ----------------------------------------------------------
extern "C" void kernel_launch(void* const* d_in, const int* in_sizes, int n_in,
                              void* d_out, int out_size) {
    (void)in_sizes; (void)n_in; (void)out_size;
    const float* x    = (const float*)d_in[0];
    const float* Wih  = (const float*)d_in[1];
    const float* Whh  = (const float*)d_in[2];
    const float* bih  = (const float*)d_in[3];
    const float* bhh  = (const float*)d_in[4];
    const float* fc_w = (const float*)d_in[5];
    const float* fc_b = (const float*)d_in[6];

    cudaFuncSetAttribute(lstm_kernel, cudaFuncAttributeMaxDynamicSharedMemorySize, SMEM_TOTAL);
    prep_kernel<<<2048, 256>>>(x, Wih, Whh, bih, bhh);
    lstm_kernel<<<NCTA, NTHR, SMEM_TOTAL>>>();
    fc_kernel<<<B_, O_>>>(fc_w, fc_b, (float*)d_out);
}

// round 12
// speedup vs baseline: 1.5358x; 1.1036x over previous
#include <cuda_runtime.h>
#include <cuda_fp16.h>
#include <cstdint>

#define B_   64
#define T_   512
#define H_   1024
#define L_   4
#define O_   256
#define NCTA 128
#define NTHR 256

#define KC      256                        // K per chunk
#define NCHUNK  8                          // 2048 / 256
#define WSTG    65536                      // W tile 128 rows x 512B
#define ASTG    32768                      // A tile  64 rows x 512B
#define STG     (WSTG + ASTG)              // 98304 per stage
#define OFF_SG  0                          // gate preacts overlay stage 0
#define OFF_SC  (2 * STG)                  // 196608 : cell state 64x32 f32
#define SMEM_TOTAL (OFF_SC + 8192)         // 204800

// XOR-swizzled index into sG: 2-way-optimal float2 stores, conflict-free reads
#define SGIDX(m, n) (((m) << 7) + ((n) ^ (((m) & 3) << 3)))

// ---------------- scratch (static device globals; no allocation) ----------------
__device__ __half g_Wc[(size_t)L_ * 32 * 128 * 2048];  // [l][s][j=128][k=2048] fp16
__device__ __half g_x[(size_t)T_ * B_ * H_];           // x fp16, [t][b][d]
__device__ __half g_h[2 * L_ * B_ * H_];               // h fp16, [parity][l][b][h]
__device__ float  g_bias[L_ * 4 * H_];                 // bih + bhh
__device__ float  g_h3[B_ * H_];                       // final layer-3 h (fp32)
__device__ unsigned g_barGen;
__device__ unsigned g_barCnt;

// ---------------- helpers --------------------------------------------------------
__device__ __forceinline__ uint32_t smem_u32(const void* p) {
    uint32_t a;
    asm("{ .reg .u64 t; cvta.to.shared.u64 t, %1; cvt.u32.u64 %0, t; }" : "=r"(a) : "l"(p));
    return a;
}
__device__ __forceinline__ void cpa16(uint32_t dst, const void* src) {
    asm volatile("cp.async.cg.shared.global [%0], [%1], 16;" :: "r"(dst), "l"(src) : "memory");
}
__device__ __forceinline__ void cp_commit() {
    asm volatile("cp.async.commit_group;" ::: "memory");
}
__device__ __forceinline__ void cp_wait0() {
    asm volatile("cp.async.wait_group 0;" ::: "memory");
}
__device__ __forceinline__ void ldsm4(uint32_t* r, uint32_t a) {
    asm volatile("ldmatrix.sync.aligned.m8n8.x4.shared.b16 {%0,%1,%2,%3}, [%4];"
                 : "=r"(r[0]), "=r"(r[1]), "=r"(r[2]), "=r"(r[3]) : "r"(a));
}
__device__ __forceinline__ void mma16816(float* c, const uint32_t* a, uint32_t b0, uint32_t b1) {
    asm volatile(
        "mma.sync.aligned.m16n8k16.row.col.f32.f16.f16.f32 "
        "{%0,%1,%2,%3}, {%4,%5,%6,%7}, {%8,%9}, {%0,%1,%2,%3};\n"
        : "+f"(c[0]), "+f"(c[1]), "+f"(c[2]), "+f"(c[3])
        : "r"(a[0]), "r"(a[1]), "r"(a[2]), "r"(a[3]), "r"(b0), "r"(b1));
}
__device__ __forceinline__ float tanh_fast(float x) {
    float y;
    asm("tanh.approx.f32 %0, %1;" : "=f"(y) : "f"(x));
    return y;
}
__device__ __forceinline__ float sig_fast(float x) {
    return 0.5f * tanh_fast(0.5f * x) + 0.5f;
}

// ---------------- split grid barrier (128 CTAs, 1/SM, all resident) --------------
__device__ __forceinline__ unsigned bar_arrive() {
    __threadfence();
    __syncthreads();
    unsigned gen = 0;
    if (threadIdx.x == 0) {
        gen = *((volatile unsigned*)&g_barGen);
        __threadfence();
        unsigned prev = atomicAdd(&g_barCnt, 1u);
        if (prev == NCTA - 1) {
            g_barCnt = 0;
            __threadfence();
            atomicAdd(&g_barGen, 1u);
        }
    }
    return gen;
}
__device__ __forceinline__ void bar_wait(unsigned gen) {
    if (threadIdx.x == 0) {
        while (*((volatile unsigned*)&g_barGen) == gen) { }
    }
    __syncthreads();
}

// ---------------- prep: weight swizzle + x fp16 + fused bias ---------------------
__global__ void prep_kernel(const float* __restrict__ x,
                            const float* __restrict__ Wih,
                            const float* __restrict__ Whh,
                            const float* __restrict__ bih,
                            const float* __restrict__ bhh) {
    long long tid = (long long)blockIdx.x * blockDim.x + threadIdx.x;
    long long stride = (long long)gridDim.x * blockDim.x;

    const long long NW = (long long)L_ * 32 * 128 * 2048;
    for (long long n = tid; n < NW; n += stride) {
        int k = (int)(n & 2047);
        int j = (int)((n >> 11) & 127);
        int s = (int)((n >> 18) & 31);
        int l = (int)(n >> 23);
        int g = j >> 5, jj = j & 31;
        int row = g * 1024 + s * 32 + jj;
        float v = (k < 1024)
            ? Wih[((long long)l * 4096 + row) * 1024 + k]
            : Whh[((long long)l * 4096 + row) * 1024 + (k - 1024)];
        g_Wc[n] = __float2half_rn(v);
    }

    const long long NX = (long long)T_ * B_ * H_;
    for (long long n = tid; n < NX; n += stride) {
        int d = (int)(n & 1023);
        int b = (int)((n >> 10) & 63);
        int t = (int)(n >> 16);
        g_x[n] = __float2half_rn(x[((long long)b * T_ + t) * H_ + d]);
    }

    for (long long n = tid; n < L_ * 4 * H_; n += stride)
        g_bias[n] = bih[n] + bhh[n];
}

// ---------------- persistent LSTM kernel -----------------------------------------
__global__ void __launch_bounds__(NTHR, 1) lstm_kernel() {
    extern __shared__ __align__(1024) char smem[];
    const uint32_t sb = smem_u32(smem);
    const int tid = threadIdx.x;
    const int lane = tid & 31;
    const int wid = tid >> 5;
    const int bid = blockIdx.x;
    const int l = bid >> 5;          // layer
    const int s = bid & 31;          // gate-column slice (32 h cols)

    float* sG = (float*)(smem + OFF_SG);  // overlays stage 0 (free at epilogue)
    float* sC = (float*)(smem + OFF_SC);  // [b=64][hc=32]

    // zero h double buffer + c state
    {
        const int total = (2 * L_ * B_ * H_) / 8;
        uint4 z = make_uint4(0, 0, 0, 0);
        for (int i = bid * NTHR + tid; i < total; i += NCTA * NTHR)
            ((uint4*)g_h)[i] = z;
        for (int i = tid; i < B_ * 32; i += NTHR) sC[i] = 0.f;
    }

    // elementwise constants
    const int hcl = tid & 31;
    const int eb0 = tid >> 5;
    float bias_g[4];
    #pragma unroll
    for (int g = 0; g < 4; ++g)
        bias_g[g] = g_bias[l * 4096 + g * 1024 + s * 32 + hcl];

    // warp / lane tiling (2x4 grid of 32x32 tiles — LDSM-minimal)
    const int wm = wid >> 2;
    const int wn = wid & 3;
    const int t8 = lane >> 3;
    const int r8 = lane & 7;
    const uint32_t swz = (uint32_t)r8;
    const uint32_t tA = (uint32_t)(t8 >> 1);
    const uint32_t tB = (uint32_t)(t8 & 1);

    uint32_t aBase[2][2], bBase[2][2];
    #pragma unroll
    for (int st = 0; st < 2; ++st) {
        uint32_t wa = sb + st * STG;
        #pragma unroll
        for (int mi = 0; mi < 2; ++mi) {
            int m = wm * 32 + mi * 16 + (t8 & 1) * 8 + r8;
            aBase[st][mi] = wa + WSTG + m * 512;
        }
        #pragma unroll
        for (int p = 0; p < 2; ++p) {
            int n = wn * 32 + p * 16 + (t8 >> 1) * 8 + r8;
            bBase[st][p] = wa + n * 512;
        }
    }

    const __half* Wbase = g_Wc + (size_t)(l * 32 + s) * 128 * 2048;

    // W staging, KC=256: 16 cpa16/thread. Tick-invariant — prefetch across barriers.
    auto issueW = [&](int kc, int st) {
        const __half* Wsrc = Wbase + kc * KC;
        uint32_t wdst = sb + st * STG;
        #pragma unroll
        for (int q = 0; q < 16; ++q) {
            int f = tid + q * 256;
            int j = f >> 5, c = f & 31;
            uint32_t d = wdst + (uint32_t)(j * 512) + ((uint32_t)(c ^ (j & 7)) << 4);
            cpa16(d, Wsrc + (size_t)j * 2048 + c * 8);
        }
    };

    // ---- initial barrier + first-tick W prefetch (uncommitted) ----
    unsigned gen = bar_arrive();
    if (l == 0) { issueW(0, 0); issueW(1, 1); }
    bar_wait(gen);

    for (int tau = 0; tau < T_ + L_ - 1; ++tau) {
        const int t = tau - l;
        if (t >= 0 && t < T_) {
            const int par = tau & 1;
            const __half* hin = g_h + (par ^ 1) * (L_ * B_ * H_);
            const __half* in  = (l == 0) ? (g_x + (size_t)t * (B_ * H_))
                                         : (hin + (l - 1) * (B_ * H_));
            const __half* rec = hin + l * (B_ * H_);

            auto issueA = [&](int kc, int st) {
                const __half* Asrc = (kc < 4) ? in : rec;
                const int kloc = (kc & 3) * KC;
                uint32_t adst = sb + st * STG + WSTG;
                #pragma unroll
                for (int q = 0; q < 8; ++q) {
                    int f = tid + q * 256;
                    int b = f >> 5, c = f & 31;
                    uint32_t d = adst + (uint32_t)(b * 512) + ((uint32_t)(c ^ (b & 7)) << 4);
                    cpa16(d, Asrc + (size_t)b * 1024 + kloc + c * 8);
                }
            };

            float acc[2][4][4];
            #pragma unroll
            for (int mi = 0; mi < 2; ++mi)
                #pragma unroll
                for (int ni = 0; ni < 4; ++ni)
                    #pragma unroll
                    for (int q = 0; q < 4; ++q) acc[mi][ni][q] = 0.f;

            // W0/W1 already in flight (issued at the barrier, uncommitted).
            issueA(0, 0); cp_commit();      // g0 = {W0, W1, A0}

            #pragma unroll
            for (int kc = 0; kc < NCHUNK; ++kc) {
                const int st = kc & 1;
                cp_wait0();            // chunk kc fully resident (this thread)
                __syncthreads();       // all threads have kc; all done computing kc-1
                if (kc + 1 < NCHUNK) {
                    if (kc + 1 >= 2) issueW(kc + 1, (kc + 1) & 1);
                    issueA(kc + 1, (kc + 1) & 1);
                    cp_commit();       // one group in flight during compute
                }

                #pragma unroll
                for (int kk = 0; kk < 16; ++kk) {
                    const uint32_t acol = (((uint32_t)(2 * kk) + tA) ^ swz) << 4;
                    const uint32_t bcol = (((uint32_t)(2 * kk) + tB) ^ swz) << 4;
                    uint32_t a[2][4], bf[2][4];
                    ldsm4(a[0], aBase[st][0] + acol);
                    ldsm4(a[1], aBase[st][1] + acol);
                    ldsm4(bf[0], bBase[st][0] + bcol);
                    ldsm4(bf[1], bBase[st][1] + bcol);
                    #pragma unroll
                    for (int mi = 0; mi < 2; ++mi) {
                        mma16816(acc[mi][0], a[mi], bf[0][0], bf[0][1]);
                        mma16816(acc[mi][1], a[mi], bf[0][2], bf[0][3]);
                        mma16816(acc[mi][2], a[mi], bf[1][0], bf[1][1]);
                        mma16816(acc[mi][3], a[mi], bf[1][2], bf[1][3]);
                    }
                }
            }

            // ---- epilogue: acc -> sG (overlays stage 0; chunk 7 used stage 1) ----
            {
                const int grp = lane >> 2, tg = lane & 3;
                #pragma unroll
                for (int mi = 0; mi < 2; ++mi)
                    #pragma unroll
                    for (int ni = 0; ni < 4; ++ni) {
                        int n = wn * 32 + ni * 8 + tg * 2;
                        int m0 = wm * 32 + mi * 16 + grp;
                        *(float2*)&sG[SGIDX(m0, n)]     = make_float2(acc[mi][ni][0], acc[mi][ni][1]);
                        *(float2*)&sG[SGIDX(m0 + 8, n)] = make_float2(acc[mi][ni][2], acc[mi][ni][3]);
                    }
            }
            __syncthreads();

            // ---- elementwise LSTM cell ----
            __half* hout = g_h + par * (L_ * B_ * H_) + l * (B_ * H_);
            #pragma unroll
            for (int b = eb0; b < 64; b += 8) {
                float ai = sG[SGIDX(b, 0 * 32 + hcl)] + bias_g[0];
                float af = sG[SGIDX(b, 1 * 32 + hcl)] + bias_g[1];
                float ag = sG[SGIDX(b, 2 * 32 + hcl)] + bias_g[2];
                float ao = sG[SGIDX(b, 3 * 32 + hcl)] + bias_g[3];
                float ig = sig_fast(ai);
                float fg = sig_fast(af);
                float gg = tanh_fast(ag);
                float og = sig_fast(ao);
                float cs = fg * sC[b * 32 + hcl] + ig * gg;
                sC[b * 32 + hcl] = cs;
                float hv = og * tanh_fast(cs);
                int go = b * 1024 + s * 32 + hcl;
                __stcg(hout + go, __float2half_rn(hv));
                if (l == 3 && t == T_ - 1) g_h3[go] = hv;
            }
        }

        // ---- barrier; next-tick W0/W1 prefetch (uncommitted) hides in the gap ----
        gen = bar_arrive();
        const int t2 = tau + 1 - l;
        if (t2 >= 0 && t2 < T_) { issueW(0, 0); issueW(1, 1); }
        bar_wait(gen);
    }
}

// ---------------- final FC: out[b][o] = h3[b] . fc_w[o] + fc_b[o] ----------------
__global__ void fc_kernel(const float* __restrict__ fc_w,
                          const float* __restrict__ fc_b,
                          float* __restrict__ out) {
    __shared__ float hs[H_];
    const int b = blockIdx.x;
    const int o = threadIdx.x;
    for (int k = o; k < H_; k += O_) hs[k] = g_h3[b * H_ + k];
    __syncthreads();
    const float* w = fc_w + (long long)o * H_;
    float a0 = 0.f, a1 = 0.f, a2 = 0.f, a3 = 0.f;
    #pragma unroll 4
    for (int k = 0; k < H_; k += 4) {
        a0 += hs[k + 0] * __ldg(w + k + 0);
        a1 += hs[k + 1] * __ldg(w + k + 1);
        a2 += hs[k + 2] * __ldg(w + k + 2);
        a3 += hs[k + 3] * __ldg(w + k + 3);
    }
    out[b * O_ + o] = fc_b[o] + ((a0 + a1) + (a2 + a3));
}

// ---------------- launch ----------------------------------------------------------
extern "C" void kernel_launch(void* const* d_in, const int* in_sizes, int n_in,
                              void* d_out, int out_size) {
    (void)in_sizes; (void)n_in; (void)out_size;
    const float* x    = (const float*)d_in[0];
    const float* Wih  = (const float*)d_in[1];
    const float* Whh  = (const float*)d_in[2];
    const float* bih  = (const float*)d_in[3];
    const float* bhh  = (const float*)d_in[4];
    const float* fc_w = (const float*)d_in[5];
    const float* fc_b = (const float*)d_in[6];

    cudaFuncSetAttribute(lstm_kernel, cudaFuncAttributeMaxDynamicSharedMemorySize, SMEM_TOTAL);
    prep_kernel<<<2048, 256>>>(x, Wih, Whh, bih, bhh);
    lstm_kernel<<<NCTA, NTHR, SMEM_TOTAL>>>();
    fc_kernel<<<B_, O_>>>(fc_w, fc_b, (float*)d_out);
}

// round 13
// speedup vs baseline: 1.5812x; 1.0296x over previous
#include <cuda_runtime.h>
#include <cuda_fp16.h>
#include <cstdint>

#define B_   64
#define T_   512
#define H_   1024
#define L_   4
#define O_   256
#define NCTA 128
#define NTHR 256
#define NBUF 8                             // h ring depth (steps of cross-layer skew)

#define KC      256                        // K per chunk
#define NCHUNK  8                          // 2048 / 256
#define WSTG    65536                      // W tile 128 rows x 512B
#define ASTG    32768                      // A tile  64 rows x 512B
#define STG     (WSTG + ASTG)              // 98304 per stage
#define OFF_SG  0                          // gate preacts overlay stage 0
#define OFF_SC  (2 * STG)                  // 196608 : cell state 64x32 f32
#define SMEM_TOTAL (OFF_SC + 8192)         // 204800

// XOR-swizzled index into sG
#define SGIDX(m, n) (((m) << 7) + ((n) ^ (((m) & 3) << 3)))

// ---------------- scratch (static device globals; no allocation) ----------------
__device__ __half g_Wc[(size_t)L_ * 32 * 128 * 2048];  // [l][s][j=128][k=2048] fp16
__device__ __half g_x[(size_t)T_ * B_ * H_];           // x fp16, [t][b][d]
__device__ __half g_h[(size_t)NBUF * L_ * B_ * H_];    // h ring, [slot][l][b][h]
__device__ float  g_bias[L_ * 4 * H_];                 // bih + bhh
__device__ float  g_h3[B_ * H_];                       // final layer-3 h (fp32)
__device__ unsigned g_done[L_];                        // per-layer step counters (32/step)
__device__ unsigned g_barGen;
__device__ unsigned g_barCnt;

// ---------------- helpers --------------------------------------------------------
__device__ __forceinline__ uint32_t smem_u32(const void* p) {
    uint32_t a;
    asm("{ .reg .u64 t; cvta.to.shared.u64 t, %1; cvt.u32.u64 %0, t; }" : "=r"(a) : "l"(p));
    return a;
}
__device__ __forceinline__ void cpa16(uint32_t dst, const void* src) {
    asm volatile("cp.async.cg.shared.global [%0], [%1], 16;" :: "r"(dst), "l"(src) : "memory");
}
__device__ __forceinline__ void cp_commit() {
    asm volatile("cp.async.commit_group;" ::: "memory");
}
__device__ __forceinline__ void cp_wait0() {
    asm volatile("cp.async.wait_group 0;" ::: "memory");
}
__device__ __forceinline__ void ldsm4(uint32_t* r, uint32_t a) {
    asm volatile("ldmatrix.sync.aligned.m8n8.x4.shared.b16 {%0,%1,%2,%3}, [%4];"
                 : "=r"(r[0]), "=r"(r[1]), "=r"(r[2]), "=r"(r[3]) : "r"(a));
}
__device__ __forceinline__ void mma16816(float* c, const uint32_t* a, uint32_t b0, uint32_t b1) {
    asm volatile(
        "mma.sync.aligned.m16n8k16.row.col.f32.f16.f16.f32 "
        "{%0,%1,%2,%3}, {%4,%5,%6,%7}, {%8,%9}, {%0,%1,%2,%3};\n"
        : "+f"(c[0]), "+f"(c[1]), "+f"(c[2]), "+f"(c[3])
        : "r"(a[0]), "r"(a[1]), "r"(a[2]), "r"(a[3]), "r"(b0), "r"(b1));
}
__device__ __forceinline__ float tanh_fast(float x) {
    float y;
    asm("tanh.approx.f32 %0, %1;" : "=f"(y) : "f"(x));
    return y;
}
__device__ __forceinline__ float sig_fast(float x) {
    return 0.5f * tanh_fast(0.5f * x) + 0.5f;
}

// ---------------- startup grid barrier (replay-safe, used once) ------------------
__device__ __forceinline__ void gridBarrier() {
    __threadfence();
    __syncthreads();
    if (threadIdx.x == 0) {
        unsigned gen = *((volatile unsigned*)&g_barGen);
        __threadfence();
        unsigned prev = atomicAdd(&g_barCnt, 1u);
        if (prev == NCTA - 1) {
            g_barCnt = 0;
            __threadfence();
            atomicAdd(&g_barGen, 1u);
        } else {
            while (*((volatile unsigned*)&g_barGen) == gen) { }
        }
    }
    __syncthreads();
}

// spin until *p >= v (tid 0 only; caller syncs)
__device__ __forceinline__ void waitGE(const unsigned* p, unsigned v) {
    while (*((volatile const unsigned*)p) < v) { }
}

// ---------------- prep: weight swizzle + x fp16 + fused bias ---------------------
__global__ void prep_kernel(const float* __restrict__ x,
                            const float* __restrict__ Wih,
                            const float* __restrict__ Whh,
                            const float* __restrict__ bih,
                            const float* __restrict__ bhh) {
    long long tid = (long long)blockIdx.x * blockDim.x + threadIdx.x;
    long long stride = (long long)gridDim.x * blockDim.x;

    const long long NW = (long long)L_ * 32 * 128 * 2048;
    for (long long n = tid; n < NW; n += stride) {
        int k = (int)(n & 2047);
        int j = (int)((n >> 11) & 127);
        int s = (int)((n >> 18) & 31);
        int l = (int)(n >> 23);
        int g = j >> 5, jj = j & 31;
        int row = g * 1024 + s * 32 + jj;
        float v = (k < 1024)
            ? Wih[((long long)l * 4096 + row) * 1024 + k]
            : Whh[((long long)l * 4096 + row) * 1024 + (k - 1024)];
        g_Wc[n] = __float2half_rn(v);
    }

    const long long NX = (long long)T_ * B_ * H_;
    for (long long n = tid; n < NX; n += stride) {
        int d = (int)(n & 1023);
        int b = (int)((n >> 10) & 63);
        int t = (int)(n >> 16);
        g_x[n] = __float2half_rn(x[((long long)b * T_ + t) * H_ + d]);
    }

    for (long long n = tid; n < L_ * 4 * H_; n += stride)
        g_bias[n] = bih[n] + bhh[n];
}

// ---------------- persistent LSTM kernel (dataflow-synced) -----------------------
__global__ void __launch_bounds__(NTHR, 1) lstm_kernel() {
    extern __shared__ __align__(1024) char smem[];
    const uint32_t sb = smem_u32(smem);
    const int tid = threadIdx.x;
    const int lane = tid & 31;
    const int wid = tid >> 5;
    const int bid = blockIdx.x;
    const int l = bid >> 5;          // layer
    const int s = bid & 31;          // gate-column slice (32 h cols)

    float* sG = (float*)(smem + OFF_SG);  // overlays stage 0
    float* sC = (float*)(smem + OFF_SC);  // [b=64][hc=32]

    // reset counters (CTA 0) + zero h ring + c state, then one startup barrier
    if (bid == 0 && tid < L_) g_done[tid] = 0u;
    {
        const int total = (NBUF * L_ * B_ * H_) / 8;   // uint4 count
        uint4 z = make_uint4(0, 0, 0, 0);
        for (int i = bid * NTHR + tid; i < total; i += NCTA * NTHR)
            ((uint4*)g_h)[i] = z;
        for (int i = tid; i < B_ * 32; i += NTHR) sC[i] = 0.f;
    }

    // elementwise constants
    const int hcl = tid & 31;
    const int eb0 = tid >> 5;
    float bias_g[4];
    #pragma unroll
    for (int g = 0; g < 4; ++g)
        bias_g[g] = g_bias[l * 4096 + g * 1024 + s * 32 + hcl];

    // warp / lane tiling (2x4 grid of 32x32 tiles)
    const int wm = wid >> 2;
    const int wn = wid & 3;
    const int t8 = lane >> 3;
    const int r8 = lane & 7;
    const uint32_t swz = (uint32_t)r8;
    const uint32_t tA = (uint32_t)(t8 >> 1);
    const uint32_t tB = (uint32_t)(t8 & 1);

    uint32_t aBase[2][2], bBase[2][2];
    #pragma unroll
    for (int st = 0; st < 2; ++st) {
        uint32_t wa = sb + st * STG;
        #pragma unroll
        for (int mi = 0; mi < 2; ++mi) {
            int m = wm * 32 + mi * 16 + (t8 & 1) * 8 + r8;
            aBase[st][mi] = wa + WSTG + m * 512;
        }
        #pragma unroll
        for (int p = 0; p < 2; ++p) {
            int n = wn * 32 + p * 16 + (t8 >> 1) * 8 + r8;
            bBase[st][p] = wa + n * 512;
        }
    }

    const __half* Wbase = g_Wc + (size_t)(l * 32 + s) * 128 * 2048;

    auto issueW = [&](int kc, int st) {
        const __half* Wsrc = Wbase + kc * KC;
        uint32_t wdst = sb + st * STG;
        #pragma unroll
        for (int q = 0; q < 16; ++q) {
            int f = tid + q * 256;
            int j = f >> 5, c = f & 31;
            uint32_t d = wdst + (uint32_t)(j * 512) + ((uint32_t)(c ^ (j & 7)) << 4);
            cpa16(d, Wsrc + (size_t)j * 2048 + c * 8);
        }
    };

    // first-step W prefetch (uncommitted), then startup barrier
    issueW(0, 0); issueW(1, 1);
    gridBarrier();

    for (int t = 0; t < T_; ++t) {
        // ---- dataflow waits (tid 0 spins, others park at the sync) ----
        if (tid == 0) {
            if (l > 0) waitGE(&g_done[l - 1], 32u * (unsigned)(t + 1)); // upstream h(t)
            if (t > 0) waitGE(&g_done[l], 32u * (unsigned)t);           // peers' h(t-1)
            if (l < 3 && t >= NBUF - 1)                                  // WAR on slot reuse
                waitGE(&g_done[l + 1], 32u * (unsigned)(t - (NBUF - 1) + 1));
        }
        __syncthreads();
        __threadfence();   // acquire: order subsequent reads after counter observation

        const int slot  = t & (NBUF - 1);
        const int pslot = (t - 1) & (NBUF - 1);
        const __half* in  = (l == 0) ? (g_x + (size_t)t * (B_ * H_))
                                     : (g_h + ((size_t)slot * L_ + (l - 1)) * (B_ * H_));
        const __half* rec = g_h + ((size_t)pslot * L_ + l) * (B_ * H_);

        auto issueA = [&](int kc, int st) {
            const __half* Asrc = (kc < 4) ? in : rec;
            const int kloc = (kc & 3) * KC;
            uint32_t adst = sb + st * STG + WSTG;
            #pragma unroll
            for (int q = 0; q < 8; ++q) {
                int f = tid + q * 256;
                int b = f >> 5, c = f & 31;
                uint32_t d = adst + (uint32_t)(b * 512) + ((uint32_t)(c ^ (b & 7)) << 4);
                cpa16(d, Asrc + (size_t)b * 1024 + kloc + c * 8);
            }
        };

        float acc[2][4][4];
        #pragma unroll
        for (int mi = 0; mi < 2; ++mi)
            #pragma unroll
            for (int ni = 0; ni < 4; ++ni)
                #pragma unroll
                for (int q = 0; q < 4; ++q) acc[mi][ni][q] = 0.f;

        // W0/W1 already in flight (issued at end of previous step, uncommitted)
        issueA(0, 0); cp_commit();      // g0 = {W0, W1, A0}

        #pragma unroll
        for (int kc = 0; kc < NCHUNK; ++kc) {
            const int st = kc & 1;
            cp_wait0();
            __syncthreads();
            if (kc + 1 < NCHUNK) {
                if (kc + 1 >= 2) issueW(kc + 1, (kc + 1) & 1);
                issueA(kc + 1, (kc + 1) & 1);
                cp_commit();
            }

            #pragma unroll
            for (int kk = 0; kk < 16; ++kk) {
                const uint32_t acol = (((uint32_t)(2 * kk) + tA) ^ swz) << 4;
                const uint32_t bcol = (((uint32_t)(2 * kk) + tB) ^ swz) << 4;
                uint32_t a[2][4], bf[2][4];
                ldsm4(a[0], aBase[st][0] + acol);
                ldsm4(a[1], aBase[st][1] + acol);
                ldsm4(bf[0], bBase[st][0] + bcol);
                ldsm4(bf[1], bBase[st][1] + bcol);
                #pragma unroll
                for (int mi = 0; mi < 2; ++mi) {
                    mma16816(acc[mi][0], a[mi], bf[0][0], bf[0][1]);
                    mma16816(acc[mi][1], a[mi], bf[0][2], bf[0][3]);
                    mma16816(acc[mi][2], a[mi], bf[1][0], bf[1][1]);
                    mma16816(acc[mi][3], a[mi], bf[1][2], bf[1][3]);
                }
            }
        }

        // ---- epilogue: acc -> sG (overlays stage 0; chunk 7 used stage 1) ----
        {
            const int grp = lane >> 2, tg = lane & 3;
            #pragma unroll
            for (int mi = 0; mi < 2; ++mi)
                #pragma unroll
                for (int ni = 0; ni < 4; ++ni) {
                    int n = wn * 32 + ni * 8 + tg * 2;
                    int m0 = wm * 32 + mi * 16 + grp;
                    *(float2*)&sG[SGIDX(m0, n)]     = make_float2(acc[mi][ni][0], acc[mi][ni][1]);
                    *(float2*)&sG[SGIDX(m0 + 8, n)] = make_float2(acc[mi][ni][2], acc[mi][ni][3]);
                }
        }
        __syncthreads();

        // ---- elementwise LSTM cell ----
        __half* hout = g_h + ((size_t)slot * L_ + l) * (B_ * H_);
        #pragma unroll
        for (int b = eb0; b < 64; b += 8) {
            float ai = sG[SGIDX(b, 0 * 32 + hcl)] + bias_g[0];
            float af = sG[SGIDX(b, 1 * 32 + hcl)] + bias_g[1];
            float ag = sG[SGIDX(b, 2 * 32 + hcl)] + bias_g[2];
            float ao = sG[SGIDX(b, 3 * 32 + hcl)] + bias_g[3];
            float ig = sig_fast(ai);
            float fg = sig_fast(af);
            float gg = tanh_fast(ag);
            float og = sig_fast(ao);
            float cs = fg * sC[b * 32 + hcl] + ig * gg;
            sC[b * 32 + hcl] = cs;
            float hv = og * tanh_fast(cs);
            int go = b * 1024 + s * 32 + hcl;
            __stcg(hout + go, __float2half_rn(hv));
            if (l == 3 && t == T_ - 1) g_h3[go] = hv;
        }
        __syncthreads();                 // all h writes of this CTA issued

        if (tid == 0) {
            __threadfence();             // release: h visible before count
            atomicAdd(&g_done[l], 1u);
        }

        // next-step W prefetch (uncommitted) — overlaps the dataflow waits
        if (t + 1 < T_) { issueW(0, 0); issueW(1, 1); }
    }
}

// ---------------- final FC: out[b][o] = h3[b] . fc_w[o] + fc_b[o] ----------------
__global__ void fc_kernel(const float* __restrict__ fc_w,
                          const float* __restrict__ fc_b,
                          float* __restrict__ out) {
    __shared__ float hs[H_];
    const int b = blockIdx.x;
    const int o = threadIdx.x;
    for (int k = o; k < H_; k += O_) hs[k] = g_h3[b * H_ + k];
    __syncthreads();
    const float* w = fc_w + (long long)o * H_;
    float a0 = 0.f, a1 = 0.f, a2 = 0.f, a3 = 0.f;
    #pragma unroll 4
    for (int k = 0; k < H_; k += 4) {
        a0 += hs[k + 0] * __ldg(w + k + 0);
        a1 += hs[k + 1] * __ldg(w + k + 1);
        a2 += hs[k + 2] * __ldg(w + k + 2);
        a3 += hs[k + 3] * __ldg(w + k + 3);
    }
    out[b * O_ + o] = fc_b[o] + ((a0 + a1) + (a2 + a3));
}

// ---------------- launch ----------------------------------------------------------
extern "C" void kernel_launch(void* const* d_in, const int* in_sizes, int n_in,
                              void* d_out, int out_size) {
    (void)in_sizes; (void)n_in; (void)out_size;
    const float* x    = (const float*)d_in[0];
    const float* Wih  = (const float*)d_in[1];
    const float* Whh  = (const float*)d_in[2];
    const float* bih  = (const float*)d_in[3];
    const float* bhh  = (const float*)d_in[4];
    const float* fc_w = (const float*)d_in[5];
    const float* fc_b = (const float*)d_in[6];

    cudaFuncSetAttribute(lstm_kernel, cudaFuncAttributeMaxDynamicSharedMemorySize, SMEM_TOTAL);
    prep_kernel<<<2048, 256>>>(x, Wih, Whh, bih, bhh);
    lstm_kernel<<<NCTA, NTHR, SMEM_TOTAL>>>();
    fc_kernel<<<B_, O_>>>(fc_w, fc_b, (float*)d_out);
}